// round 4
// baseline (speedup 1.0000x reference)
#include <cuda_runtime.h>
#include <cuda_bf16.h>

#define N_PATHS 2048
#define N_STEPS 512
#define N_FWD   40
#define DT      (1.0f / 512.0f)
#define SHIFT   0.02f
#define LOG2E   1.4426950408889634f
#define N_CHUNK 8
#define CHUNK_T (N_STEPS / N_CHUNK)   // 64

// ---------------- device scratch ----------------
__device__ float  g_cw2[N_STEPS];               // inclusive prefix sum of w^2
__device__ float4 g_fbm4[N_PATHS * N_STEPS];    // fbm4[p][t][0..3]

// ---------------- f32x2 helpers ----------------
__device__ __forceinline__ unsigned long long f2pack(float lo, float hi) {
    unsigned long long r;
    asm("mov.b64 %0, {%1, %2};" : "=l"(r) : "f"(lo), "f"(hi));
    return r;
}
__device__ __forceinline__ void ffma2(unsigned long long& d, unsigned long long a, unsigned long long b) {
    asm("fma.rn.f32x2 %0, %1, %2, %0;" : "+l"(d) : "l"(a), "l"(b));
}
__device__ __forceinline__ float2 f2unpack(unsigned long long v) {
    float2 r;
    asm("mov.b64 {%0, %1}, %2;" : "=f"(r.x), "=f"(r.y) : "l"(v));
    return r;
}

// Toeplitz weight, cancellation-free in fp32:
// w[j] = ((j+1)^0.6 - j^0.6)/0.6 * 2^3.6 / Gamma(0.6)
__device__ __forceinline__ float toeplitz_w(int j) {
    const float scale = 12.125732f / 1.4891922f;   // 2^3.6 / Gamma(0.6)
    float num;
    if (j == 0) {
        num = 1.0f / 0.6f;
    } else {
        float fj = (float)j;
        float p6 = exp2f(0.6f * log2f(fj));            // j^0.6
        float em = expm1f(0.6f * log1pf(1.0f / fj));   // (1+1/j)^0.6 - 1
        num = p6 * em * (1.0f / 0.6f);
    }
    return num * scale;
}

// Warp -> t-block permutation balancing trip counts across SMSPs.
__device__ __constant__ int c_tb[16] = {0, 2, 4, 6, 15, 13, 11, 9,
                                        1, 3, 5, 7, 14, 12, 10, 8};

// ---------------- kernel 1: causal Toeplitz convolution (fBM) ----------------
__global__ __launch_bounds__(512, 2) void k_conv(const float* __restrict__ dz) {
    __shared__ ulonglong2 sdz[4][N_STEPS];          // 32 KB
    __shared__ unsigned long long sw2[N_STEPS];     //  4 KB
    __shared__ float scw[N_STEPS];                  //  2 KB (scan scratch, block 0)

    int p0   = blockIdx.x * 4;
    int wid  = threadIdx.x >> 5;
    int lane = threadIdx.x & 31;
    int t    = c_tb[wid] * 32 + lane;

    float wv = toeplitz_w(t);
    sw2[t] = f2pack(wv, wv);

    const float4* dzv = (const float4*)dz;
    #pragma unroll
    for (int q = 0; q < 4; ++q) {
        float4 d = dzv[(size_t)(p0 + q) * N_STEPS + t];
        ulonglong2 u;
        u.x = f2pack(d.x, d.y);
        u.y = f2pack(d.z, d.w);
        sdz[q][t] = u;
    }

    if (blockIdx.x == 0) {
        scw[t] = wv * wv;
        __syncthreads();
        #pragma unroll
        for (int off = 1; off < N_STEPS; off <<= 1) {
            float v = scw[t];
            if (t >= off) v += scw[t - off];
            __syncthreads();
            scw[t] = v;
            __syncthreads();
        }
        g_cw2[t] = scw[t];
    }
    __syncthreads();

    unsigned long long acc01[4] = {0ull, 0ull, 0ull, 0ull};
    unsigned long long acc23[4] = {0ull, 0ull, 0ull, 0ull};

    int lo = t & ~31;

    #pragma unroll 4
    for (int s = 0; s <= lo; ++s) {
        unsigned long long ww = sw2[t - s];
        #pragma unroll
        for (int q = 0; q < 4; ++q) {
            ulonglong2 x = sdz[q][s];
            ffma2(acc01[q], x.x, ww);
            ffma2(acc23[q], x.y, ww);
        }
    }
    #pragma unroll
    for (int d = 1; d < 32; ++d) {
        int s = lo + d;
        if (s <= t) {
            unsigned long long ww = sw2[t - s];
            #pragma unroll
            for (int q = 0; q < 4; ++q) {
                ulonglong2 x = sdz[q][s];
                ffma2(acc01[q], x.x, ww);
                ffma2(acc23[q], x.y, ww);
            }
        }
    }

    #pragma unroll
    for (int q = 0; q < 4; ++q) {
        float2 r01 = f2unpack(acc01[q]);
        float2 r23 = f2unpack(acc23[q]);
        g_fbm4[(size_t)(p0 + q) * N_STEPS + t] = make_float4(r01.x, r01.y, r23.x, r23.y);
    }
}

// ---------------- kernel 2: per-path chunked scan ----------------
// One block = one path. 320 threads = (chunk c 0..7) x (forward n 0..39).
// Phase 1: compute dF for my 64-step chunk into shared + chunk partial sum.
// Phase 2: offset = F0 + sum of earlier chunks' partials.
// Phase 3: sequential accumulate within chunk from shared, coalesced stores.
__global__ __launch_bounds__(320, 2) void k_path(
    const float* __restrict__ dz,
    const float* __restrict__ F0,
    const float* __restrict__ alphas,
    const float* __restrict__ rhos,
    const float* __restrict__ nus,
    const float* __restrict__ tau,
    const float* __restrict__ L,
    const float* __restrict__ Lam,
    float* __restrict__ out)
{
    extern __shared__ float sdf[];                 // [N_STEPS][N_FWD] = 80 KB
    __shared__ float scw[N_STEPS];                 // 2 KB
    __shared__ float spart[N_CHUNK * N_FWD];       // 1.25 KB

    int u = threadIdx.x;            // 0..319
    int c = u / N_FWD;              // chunk
    int n = u - c * N_FWD;          // forward index (consecutive lanes -> consecutive n)
    int p = blockIdx.x;

    for (int i = u; i < N_STEPS; i += 320) scw[i] = g_cw2[i];

    // per-n constants
    float f0n = F0[n];
    float vs  = alphas[n] * sqrtf(fabsf(f0n + SHIFT));
    float rho = rhos[n];
    float nu  = nus[n];
    float sq  = sqrtf(fmaxf(1.f - rho * rho, 0.f));
    float l0 = L[n * 3 + 0], l1 = L[n * 3 + 1], l2 = L[n * 3 + 2];
    float a0 = nu * rho * l0 * LOG2E;
    float a1 = nu * rho * l1 * LOG2E;
    float a2 = nu * rho * l2 * LOG2E;
    float a3 = nu * sq * LOG2E;
    float bb = 0.5f * nu * nu * DT * LOG2E;
    float w0 = vs * l0, w1 = vs * l1, w2 = vs * l2;

    float mdot = 0.f;
    for (int m = 0; m < N_FWD; ++m) {
        float f0m = F0[m];
        float vsm = alphas[m] * sqrtf(fabsf(f0m + SHIFT));
        float om  = tau[m] * vsm / (1.f + tau[m] * f0m);
        mdot = fmaf(Lam[n * N_FWD + m], om, mdot);
    }
    float mu0dt = -vs * mdot * DT;

    __syncthreads();   // scw ready

    const float4* fb  = &g_fbm4[(size_t)p * N_STEPS];
    const float4* dzp = (const float4*)dz + (size_t)p * N_STEPS;

    // ---- phase 1: dF for my chunk -> shared; partial sum ----
    int t0 = c * CHUNK_T;
    float psum = 0.f;
    #pragma unroll 4
    for (int i = 0; i < CHUNK_T; ++i) {
        int t = t0 + i;
        float4 f = fb[t];
        float4 d = dzp[t];
        float arg = fmaf(a0, f.x,
                    fmaf(a1, f.y,
                    fmaf(a2, f.z,
                    fmaf(a3, f.w, -bb * scw[t]))));
        float uv;
        asm("ex2.approx.f32 %0, %1;" : "=f"(uv) : "f"(arg));
        float wr = fmaf(w0, d.x, fmaf(w1, d.y, w2 * d.z));
        float dF = uv * fmaf(mu0dt, uv, wr);
        sdf[t * N_FWD + n] = dF;
        psum += dF;
    }
    spart[c * N_FWD + n] = psum;
    __syncthreads();

    // ---- phase 2: chunk offset ----
    float acc = f0n;
    for (int cc = 0; cc < c; ++cc) acc += spart[cc * N_FWD + n];

    // ---- phase 3: sequential scan within chunk + stores ----
    float* op = out + (size_t)p * 513 * N_FWD + n;
    if (c == 0) __stcs(op, f0n);                    // row 0 = F0
    op += (size_t)(t0 + 1) * N_FWD;
    #pragma unroll 4
    for (int i = 0; i < CHUNK_T; ++i) {
        acc += sdf[(t0 + i) * N_FWD + n];
        __stcs(op, acc);
        op += N_FWD;
    }
}

extern "C" void kernel_launch(void* const* d_in, const int* in_sizes, int n_in,
                              void* d_out, int out_size) {
    const float* dz     = (const float*)d_in[0];
    const float* F0     = (const float*)d_in[1];
    const float* alphas = (const float*)d_in[2];
    const float* rhos   = (const float*)d_in[3];
    const float* nus    = (const float*)d_in[4];
    const float* tau    = (const float*)d_in[5];
    const float* L      = (const float*)d_in[6];
    const float* Lam    = (const float*)d_in[7];
    float* out = (float*)d_out;

    static int smem_set = 0;
    if (!smem_set) {
        cudaFuncSetAttribute(k_path, cudaFuncAttributeMaxDynamicSharedMemorySize,
                             N_STEPS * N_FWD * (int)sizeof(float));
        smem_set = 1;
    }

    k_conv<<<N_PATHS / 4, N_STEPS>>>(dz);
    k_path<<<N_PATHS, 320, N_STEPS * N_FWD * sizeof(float)>>>(
        dz, F0, alphas, rhos, nus, tau, L, Lam, out);
}

// round 5
// speedup vs baseline: 1.2115x; 1.2115x over previous
#include <cuda_runtime.h>
#include <cuda_bf16.h>

#define N_PATHS 2048
#define N_STEPS 512
#define N_FWD   40
#define DT      (1.0f / 512.0f)
#define SHIFT   0.02f
#define LOG2E   1.4426950408889634f
#define N_CHUNK 8
#define CHUNK_T (N_STEPS / N_CHUNK)   // 64

// ---------------- device scratch ----------------
__device__ float  g_cw2[N_STEPS];               // inclusive prefix sum of w^2
__device__ float4 g_fbm4[N_PATHS * N_STEPS];    // fbm4[p][t][0..3]

// ---------------- f32x2 helpers ----------------
__device__ __forceinline__ unsigned long long f2pack(float lo, float hi) {
    unsigned long long r;
    asm("mov.b64 %0, {%1, %2};" : "=l"(r) : "f"(lo), "f"(hi));
    return r;
}
__device__ __forceinline__ void ffma2(unsigned long long& d, unsigned long long a, unsigned long long b) {
    asm("fma.rn.f32x2 %0, %1, %2, %0;" : "+l"(d) : "l"(a), "l"(b));
}
__device__ __forceinline__ float2 f2unpack(unsigned long long v) {
    float2 r;
    asm("mov.b64 {%0, %1}, %2;" : "=f"(r.x), "=f"(r.y) : "l"(v));
    return r;
}

// Toeplitz weight, cancellation-free in fp32:
// w[j] = ((j+1)^0.6 - j^0.6)/0.6 * 2^3.6 / Gamma(0.6)
__device__ __forceinline__ float toeplitz_w(int j) {
    const float scale = 12.125732f / 1.4891922f;   // 2^3.6 / Gamma(0.6)
    float num;
    if (j == 0) {
        num = 1.0f / 0.6f;
    } else {
        float fj = (float)j;
        float p6 = exp2f(0.6f * log2f(fj));            // j^0.6
        float em = expm1f(0.6f * log1pf(1.0f / fj));   // (1+1/j)^0.6 - 1
        num = p6 * em * (1.0f / 0.6f);
    }
    return num * scale;
}

// Warp -> t-block permutation balancing trip counts across SMSPs.
__device__ __constant__ int c_tb[16] = {0, 2, 4, 6, 15, 13, 11, 9,
                                        1, 3, 5, 7, 14, 12, 10, 8};

// ---------------- kernel 1: causal Toeplitz convolution (fBM) ----------------
__global__ __launch_bounds__(512, 2) void k_conv(const float* __restrict__ dz) {
    __shared__ ulonglong2 sdz[4][N_STEPS];          // 32 KB
    __shared__ unsigned long long sw2[N_STEPS];     //  4 KB
    __shared__ float scw[N_STEPS];                  //  2 KB (scan scratch, block 0)

    int p0   = blockIdx.x * 4;
    int wid  = threadIdx.x >> 5;
    int lane = threadIdx.x & 31;
    int t    = c_tb[wid] * 32 + lane;

    float wv = toeplitz_w(t);
    sw2[t] = f2pack(wv, wv);

    const float4* dzv = (const float4*)dz;
    #pragma unroll
    for (int q = 0; q < 4; ++q) {
        float4 d = dzv[(size_t)(p0 + q) * N_STEPS + t];
        ulonglong2 u;
        u.x = f2pack(d.x, d.y);
        u.y = f2pack(d.z, d.w);
        sdz[q][t] = u;
    }

    if (blockIdx.x == 0) {
        scw[t] = wv * wv;
        __syncthreads();
        #pragma unroll
        for (int off = 1; off < N_STEPS; off <<= 1) {
            float v = scw[t];
            if (t >= off) v += scw[t - off];
            __syncthreads();
            scw[t] = v;
            __syncthreads();
        }
        g_cw2[t] = scw[t];
    }
    __syncthreads();

    unsigned long long acc01[4] = {0ull, 0ull, 0ull, 0ull};
    unsigned long long acc23[4] = {0ull, 0ull, 0ull, 0ull};

    int lo = t & ~31;

    #pragma unroll 4
    for (int s = 0; s <= lo; ++s) {
        unsigned long long ww = sw2[t - s];
        #pragma unroll
        for (int q = 0; q < 4; ++q) {
            ulonglong2 x = sdz[q][s];
            ffma2(acc01[q], x.x, ww);
            ffma2(acc23[q], x.y, ww);
        }
    }
    #pragma unroll
    for (int d = 1; d < 32; ++d) {
        int s = lo + d;
        if (s <= t) {
            unsigned long long ww = sw2[t - s];
            #pragma unroll
            for (int q = 0; q < 4; ++q) {
                ulonglong2 x = sdz[q][s];
                ffma2(acc01[q], x.x, ww);
                ffma2(acc23[q], x.y, ww);
            }
        }
    }

    #pragma unroll
    for (int q = 0; q < 4; ++q) {
        float2 r01 = f2unpack(acc01[q]);
        float2 r23 = f2unpack(acc23[q]);
        g_fbm4[(size_t)(p0 + q) * N_STEPS + t] = make_float4(r01.x, r01.y, r23.x, r23.y);
    }
}

// ---------------- kernel 2: per-path chunked scan (shared-staged, recompute) --
// One block = one path, 320 threads = (chunk c 0..7) x (forward n 0..39).
// Stage A: cooperatively stage fb[p][*], dz[p][*] into shared (coalesced, once).
// Phase 1: thread (c,n): partial sum of its 64 dF values (reads = LDS broadcast).
// Phase 2: offset = F0 + earlier chunks' partials.
// Phase 3: recompute dF (bit-identical), running scan, streaming stores.
__global__ __launch_bounds__(320) void k_path(
    const float* __restrict__ dz,
    const float* __restrict__ F0,
    const float* __restrict__ alphas,
    const float* __restrict__ rhos,
    const float* __restrict__ nus,
    const float* __restrict__ tau,
    const float* __restrict__ L,
    const float* __restrict__ Lam,
    float* __restrict__ out)
{
    __shared__ float4 sfb[N_STEPS];                // 8 KB  (fbm4 of this path)
    __shared__ float4 sdzs[N_STEPS];               // 8 KB  (dz of this path)
    __shared__ float  scw[N_STEPS];                // 2 KB
    __shared__ float  spart[N_CHUNK * N_FWD];      // 1.25 KB
    __shared__ float  som[N_FWD];                  // omega0

    int u = threadIdx.x;            // 0..319
    int c = u / N_FWD;              // chunk
    int n = u - c * N_FWD;          // forward index
    int p = blockIdx.x;

    // ---- stage A: coalesced staging ----
    const float4* fb  = &g_fbm4[(size_t)p * N_STEPS];
    const float4* dzp = (const float4*)dz + (size_t)p * N_STEPS;
    sfb[u]  = fb[u];
    sdzs[u] = dzp[u];
    scw[u]  = g_cw2[u];
    if (u + 320 < N_STEPS) {
        sfb[u + 320]  = fb[u + 320];
        sdzs[u + 320] = dzp[u + 320];
        scw[u + 320]  = g_cw2[u + 320];
    }
    // omega0[m] once per block
    if (u < N_FWD) {
        float f0m = F0[u];
        float vsm = alphas[u] * sqrtf(fabsf(f0m + SHIFT));
        som[u] = tau[u] * vsm / (1.f + tau[u] * f0m);
    }

    // ---- per-n constants ----
    float f0n = F0[n];
    float vs  = alphas[n] * sqrtf(fabsf(f0n + SHIFT));
    float rho = rhos[n];
    float nu  = nus[n];
    float sq  = sqrtf(fmaxf(1.f - rho * rho, 0.f));
    float l0 = L[n * 3 + 0], l1 = L[n * 3 + 1], l2 = L[n * 3 + 2];
    float a0 = nu * rho * l0 * LOG2E;
    float a1 = nu * rho * l1 * LOG2E;
    float a2 = nu * rho * l2 * LOG2E;
    float a3 = nu * sq * LOG2E;
    float bb = 0.5f * nu * nu * DT * LOG2E;
    float w0 = vs * l0, w1 = vs * l1, w2 = vs * l2;

    __syncthreads();   // staging + som ready

    float mdot = 0.f;
    #pragma unroll 8
    for (int m = 0; m < N_FWD; ++m)
        mdot = fmaf(Lam[n * N_FWD + m], som[m], mdot);
    float mu0dt = -vs * mdot * DT;

    // ---- phase 1: partial sum of my chunk's dF ----
    int t0 = c * CHUNK_T;
    float psum = 0.f;
    #pragma unroll 4
    for (int i = 0; i < CHUNK_T; ++i) {
        int t = t0 + i;
        float4 f = sfb[t];
        float4 d = sdzs[t];
        float arg = fmaf(a0, f.x,
                    fmaf(a1, f.y,
                    fmaf(a2, f.z,
                    fmaf(a3, f.w, -bb * scw[t]))));
        float uv;
        asm("ex2.approx.f32 %0, %1;" : "=f"(uv) : "f"(arg));
        float wr = fmaf(w0, d.x, fmaf(w1, d.y, w2 * d.z));
        psum += uv * fmaf(mu0dt, uv, wr);
    }
    spart[c * N_FWD + n] = psum;
    __syncthreads();

    // ---- phase 2: chunk offset ----
    float acc = f0n;
    #pragma unroll
    for (int cc = 0; cc < N_CHUNK - 1; ++cc)
        if (cc < c) acc += spart[cc * N_FWD + n];

    // ---- phase 3: recompute dF, scan, store ----
    float* op = out + (size_t)p * 513 * N_FWD + n;
    if (c == 0) __stcs(op, f0n);                    // row 0 = F0
    op += (size_t)(t0 + 1) * N_FWD;
    #pragma unroll 4
    for (int i = 0; i < CHUNK_T; ++i) {
        int t = t0 + i;
        float4 f = sfb[t];
        float4 d = sdzs[t];
        float arg = fmaf(a0, f.x,
                    fmaf(a1, f.y,
                    fmaf(a2, f.z,
                    fmaf(a3, f.w, -bb * scw[t]))));
        float uv;
        asm("ex2.approx.f32 %0, %1;" : "=f"(uv) : "f"(arg));
        float wr = fmaf(w0, d.x, fmaf(w1, d.y, w2 * d.z));
        acc += uv * fmaf(mu0dt, uv, wr);
        __stcs(op, acc);
        op += N_FWD;
    }
}

extern "C" void kernel_launch(void* const* d_in, const int* in_sizes, int n_in,
                              void* d_out, int out_size) {
    const float* dz     = (const float*)d_in[0];
    const float* F0     = (const float*)d_in[1];
    const float* alphas = (const float*)d_in[2];
    const float* rhos   = (const float*)d_in[3];
    const float* nus    = (const float*)d_in[4];
    const float* tau    = (const float*)d_in[5];
    const float* L      = (const float*)d_in[6];
    const float* Lam    = (const float*)d_in[7];
    float* out = (float*)d_out;

    k_conv<<<N_PATHS / 4, N_STEPS>>>(dz);
    k_path<<<N_PATHS, 320>>>(dz, F0, alphas, rhos, nus, tau, L, Lam, out);
}

// round 7
// speedup vs baseline: 1.7709x; 1.4617x over previous
#include <cuda_runtime.h>
#include <cuda_bf16.h>
#include <cstdint>

#define N_PATHS 2048
#define N_STEPS 512
#define N_FWD   40
#define DT      (1.0f / 512.0f)
#define SHIFT   0.02f
#define LOG2E   1.4426950408889634f
#define N_CHUNK 8
#define CHUNK_T (N_STEPS / N_CHUNK)   // 64

#define KC      32                    // k-chunk (s dimension) per stage
#define SA      36                    // padded row stride (floats), conflict-free

// ---------------- device scratch ----------------
__device__ float  g_cw2[N_STEPS];               // inclusive prefix sum of w^2
__device__ float4 g_fbm4[N_PATHS * N_STEPS];    // fbm4[p][t][0..3]

// Toeplitz weight, cancellation-free in fp32:
// w[j] = ((j+1)^0.6 - j^0.6)/0.6 * 2^3.6 / Gamma(0.6)
__device__ __forceinline__ float toeplitz_w(int j) {
    const float scale = 12.125732f / 1.4891922f;
    float num;
    if (j == 0) {
        num = 1.0f / 0.6f;
    } else {
        float fj = (float)j;
        float p6 = exp2f(0.6f * log2f(fj));
        float em = expm1f(0.6f * log1pf(1.0f / fj));
        num = p6 * em * (1.0f / 0.6f);
    }
    return num * scale;
}

__device__ __forceinline__ uint32_t f2tf32(float f) {
    uint32_t u;
    asm("cvt.rna.tf32.f32 %0, %1;" : "=r"(u) : "f"(f));
    return u;
}

__device__ __forceinline__ void mma_tf32(float* c, const uint32_t* a, const uint32_t* b) {
    asm volatile(
        "mma.sync.aligned.m16n8k8.row.col.f32.tf32.tf32.f32 "
        "{%0,%1,%2,%3}, {%4,%5,%6,%7}, {%8,%9}, {%0,%1,%2,%3};"
        : "+f"(c[0]), "+f"(c[1]), "+f"(c[2]), "+f"(c[3])
        : "r"(a[0]), "r"(a[1]), "r"(a[2]), "r"(a[3]), "r"(b[0]), "r"(b[1]));
}

// ---------------- kernel 1: conv as triangular Toeplitz GEMM (tf32 HMMA) ----
// D[t, n=(p*4+d)] = sum_s W[t,s] * dz[p,s,d], W lower-triangular Toeplitz.
// 256 CTAs (heavy t-tiles first), 256 threads = 8 warps in 2(m) x 4(n).
__global__ __launch_bounds__(256) void k_conv_mma(const float* __restrict__ dz) {
    __shared__ uint32_t sA[128 * SA];   // W tile   (tf32 bits), rows = t
    __shared__ uint32_t sB[128 * SA];   // dz tile  (tf32 bits), rows = n, cols = k
    __shared__ float    swf[N_STEPS];
    __shared__ float    sscan[256];

    const int tid  = threadIdx.x;
    const int wid  = tid >> 5;
    const int lane = tid & 31;
    const int bid  = blockIdx.x;
    const int ti   = 3 - (bid >> 6);     // heavy tiles (ti=3) first
    const int cg   = bid & 63;
    const int p0   = cg * 32;
    const int t0   = 128 * ti;
    const int mw   = (wid >> 2) * 64;    // warp m offset (2 warps in m)
    const int nw   = (wid & 3) * 32;     // warp n offset (4 warps in n)

    for (int i = tid; i < N_STEPS; i += 256) swf[i] = toeplitz_w(i);
    __syncthreads();

    // block 0: prefix sum of w^2 -> g_cw2 (paired Hillis-Steele)
    if (bid == 0) {
        float wa = swf[2 * tid], wb = swf[2 * tid + 1];
        float w2b = wb * wb;
        sscan[tid] = wa * wa + w2b;
        __syncthreads();
        #pragma unroll
        for (int off = 1; off < 256; off <<= 1) {
            float v = sscan[tid];
            float u = (tid >= off) ? sscan[tid - off] : 0.f;
            __syncthreads();
            sscan[tid] = v + u;
            __syncthreads();
        }
        float inc = sscan[tid];
        g_cw2[2 * tid + 1] = inc;
        g_cw2[2 * tid]     = inc - w2b;
        __syncthreads();
    }

    float c[4][4][4];   // [mt][nt][frag]
    #pragma unroll
    for (int mt = 0; mt < 4; ++mt)
        #pragma unroll
        for (int nt = 0; nt < 4; ++nt)
            #pragma unroll
            for (int e = 0; e < 4; ++e) c[mt][nt][e] = 0.f;

    const float4* dzv = (const float4*)dz;
    const int n_kc = 4 * ti + 4;         // k-chunks until diagonal inclusive

    for (int kc = 0; kc < n_kc; ++kc) {
        const int s0   = KC * kc;
        const int toff = t0 - s0;
        __syncthreads();                 // previous chunk's LDS done

        // stage A: A[i][j] = w[toff + i - j] (0 if negative). 128x32 / 256 thr
        #pragma unroll
        for (int r = 0; r < 16; ++r) {
            int u = tid + 256 * r;       // u = i*32 + j
            int i = u >> 5, j = u & 31;
            int q = toff + i - j;
            float v = (q >= 0) ? swf[q] : 0.f;
            sA[i * SA + j] = f2tf32(v);
        }
        // stage B: B[n=4*pl+d][k] = dz[p0+pl][s0+k][d]. 32 paths x 32 k
        #pragma unroll
        for (int r = 0; r < 4; ++r) {
            int u  = tid + 256 * r;      // u = pl*32 + k
            int pl = u >> 5, k = u & 31;
            float4 x = dzv[(size_t)(p0 + pl) * N_STEPS + s0 + k];
            int n = 4 * pl;
            sB[(n + 0) * SA + k] = f2tf32(x.x);
            sB[(n + 1) * SA + k] = f2tf32(x.y);
            sB[(n + 2) * SA + k] = f2tf32(x.z);
            sB[(n + 3) * SA + k] = f2tf32(x.w);
        }
        __syncthreads();

        // compute: 4 k8-steps
        #pragma unroll
        for (int ks = 0; ks < 4; ++ks) {
            int kb = 8 * ks;
            uint32_t bf[4][2];
            #pragma unroll
            for (int nt = 0; nt < 4; ++nt) {
                int col = nw + 8 * nt + (lane >> 2);
                bf[nt][0] = sB[col * SA + kb + (lane & 3)];
                bf[nt][1] = sB[col * SA + kb + 4 + (lane & 3)];
            }
            #pragma unroll
            for (int mt = 0; mt < 4; ++mt) {
                int row = mw + 16 * mt + (lane >> 2);
                uint32_t af[4];
                af[0] = sA[row * SA + kb + (lane & 3)];
                af[1] = sA[(row + 8) * SA + kb + (lane & 3)];
                af[2] = sA[row * SA + kb + 4 + (lane & 3)];
                af[3] = sA[(row + 8) * SA + kb + 4 + (lane & 3)];
                #pragma unroll
                for (int nt = 0; nt < 4; ++nt)
                    mma_tf32(c[mt][nt], af, bf[nt]);
            }
        }
    }

    // epilogue: coalesced float2 stores into g_fbm4
    float2* dst = (float2*)g_fbm4;
    #pragma unroll
    for (int mt = 0; mt < 4; ++mt) {
        #pragma unroll
        for (int nt = 0; nt < 4; ++nt) {
            int row  = mw + 16 * mt + (lane >> 2);
            int col  = nw + 8 * nt + 2 * (lane & 3);
            int path = p0 + (col >> 2);
            int dp   = (col & 3) >> 1;
            size_t base = ((size_t)path * N_STEPS + t0 + row) * 2 + dp;
            dst[base]      = make_float2(c[mt][nt][0], c[mt][nt][1]);
            dst[base + 16] = make_float2(c[mt][nt][2], c[mt][nt][3]);  // row+8 => +8*2
        }
    }
}

// ---------------- kernel 2: per-path chunked scan (unchanged from R5) -------
__global__ __launch_bounds__(320) void k_path(
    const float* __restrict__ dz,
    const float* __restrict__ F0,
    const float* __restrict__ alphas,
    const float* __restrict__ rhos,
    const float* __restrict__ nus,
    const float* __restrict__ tau,
    const float* __restrict__ L,
    const float* __restrict__ Lam,
    float* __restrict__ out)
{
    __shared__ float4 sfb[N_STEPS];
    __shared__ float4 sdzs[N_STEPS];
    __shared__ float  scw[N_STEPS];
    __shared__ float  spart[N_CHUNK * N_FWD];
    __shared__ float  som[N_FWD];

    int u = threadIdx.x;
    int c = u / N_FWD;
    int n = u - c * N_FWD;
    int p = blockIdx.x;

    const float4* fb  = &g_fbm4[(size_t)p * N_STEPS];
    const float4* dzp = (const float4*)dz + (size_t)p * N_STEPS;
    sfb[u]  = fb[u];
    sdzs[u] = dzp[u];
    scw[u]  = g_cw2[u];
    if (u + 320 < N_STEPS) {
        sfb[u + 320]  = fb[u + 320];
        sdzs[u + 320] = dzp[u + 320];
        scw[u + 320]  = g_cw2[u + 320];
    }
    if (u < N_FWD) {
        float f0m = F0[u];
        float vsm = alphas[u] * sqrtf(fabsf(f0m + SHIFT));
        som[u] = tau[u] * vsm / (1.f + tau[u] * f0m);
    }

    float f0n = F0[n];
    float vs  = alphas[n] * sqrtf(fabsf(f0n + SHIFT));
    float rho = rhos[n];
    float nu  = nus[n];
    float sq  = sqrtf(fmaxf(1.f - rho * rho, 0.f));
    float l0 = L[n * 3 + 0], l1 = L[n * 3 + 1], l2 = L[n * 3 + 2];
    float a0 = nu * rho * l0 * LOG2E;
    float a1 = nu * rho * l1 * LOG2E;
    float a2 = nu * rho * l2 * LOG2E;
    float a3 = nu * sq * LOG2E;
    float bb = 0.5f * nu * nu * DT * LOG2E;
    float w0 = vs * l0, w1 = vs * l1, w2 = vs * l2;

    __syncthreads();

    float mdot = 0.f;
    #pragma unroll 8
    for (int m = 0; m < N_FWD; ++m)
        mdot = fmaf(Lam[n * N_FWD + m], som[m], mdot);
    float mu0dt = -vs * mdot * DT;

    int t0 = c * CHUNK_T;
    float psum = 0.f;
    #pragma unroll 4
    for (int i = 0; i < CHUNK_T; ++i) {
        int t = t0 + i;
        float4 f = sfb[t];
        float4 d = sdzs[t];
        float arg = fmaf(a0, f.x,
                    fmaf(a1, f.y,
                    fmaf(a2, f.z,
                    fmaf(a3, f.w, -bb * scw[t]))));
        float uv;
        asm("ex2.approx.f32 %0, %1;" : "=f"(uv) : "f"(arg));
        float wr = fmaf(w0, d.x, fmaf(w1, d.y, w2 * d.z));
        psum += uv * fmaf(mu0dt, uv, wr);
    }
    spart[c * N_FWD + n] = psum;
    __syncthreads();

    float acc = f0n;
    #pragma unroll
    for (int cc = 0; cc < N_CHUNK - 1; ++cc)
        if (cc < c) acc += spart[cc * N_FWD + n];

    float* op = out + (size_t)p * 513 * N_FWD + n;
    if (c == 0) __stcs(op, f0n);
    op += (size_t)(t0 + 1) * N_FWD;
    #pragma unroll 4
    for (int i = 0; i < CHUNK_T; ++i) {
        int t = t0 + i;
        float4 f = sfb[t];
        float4 d = sdzs[t];
        float arg = fmaf(a0, f.x,
                    fmaf(a1, f.y,
                    fmaf(a2, f.z,
                    fmaf(a3, f.w, -bb * scw[t]))));
        float uv;
        asm("ex2.approx.f32 %0, %1;" : "=f"(uv) : "f"(arg));
        float wr = fmaf(w0, d.x, fmaf(w1, d.y, w2 * d.z));
        acc += uv * fmaf(mu0dt, uv, wr);
        __stcs(op, acc);
        op += N_FWD;
    }
}

extern "C" void kernel_launch(void* const* d_in, const int* in_sizes, int n_in,
                              void* d_out, int out_size) {
    const float* dz     = (const float*)d_in[0];
    const float* F0     = (const float*)d_in[1];
    const float* alphas = (const float*)d_in[2];
    const float* rhos   = (const float*)d_in[3];
    const float* nus    = (const float*)d_in[4];
    const float* tau    = (const float*)d_in[5];
    const float* L      = (const float*)d_in[6];
    const float* Lam    = (const float*)d_in[7];
    float* out = (float*)d_out;

    k_conv_mma<<<256, 256>>>(dz);
    k_path<<<N_PATHS, 320>>>(dz, F0, alphas, rhos, nus, tau, L, Lam, out);
}